// round 1
// baseline (speedup 1.0000x reference)
#include <cuda_runtime.h>
#include <cstdint>

#define RADIUS   4
#define WIN      9
#define MAX_DISP 192
#define BATCH    2
#define H        256
#define W        512
#define HC       (H - 2*RADIUS)   // 248
#define WC       (W - 2*RADIUS)   // 504

#define TW 32
#define TH 16
#define IN_TW (TW + 2*RADIUS)     // 40
#define IN_TH (TH + 2*RADIUS)     // 24

// Census bitmasks: [img(0=L,1=R)*BATCH + b][h][w] -> 80 bits in (x,y,z), w unused.
__device__ uint4 g_census[2 * BATCH * HC * WC];
// [0] = sum of masked costs (integer-exact), [1] = count of masked pixels
__device__ unsigned int g_acc[2];

__global__ void zero_kernel() {
    g_acc[0] = 0u;
    g_acc[1] = 0u;
}

__global__ __launch_bounds__(TW * TH)
void census_kernel(const float* __restrict__ left, const float* __restrict__ right) {
    __shared__ float tile[IN_TH][IN_TW];

    const int plane = blockIdx.z;            // 0..2*BATCH-1
    const int img   = plane / BATCH;         // 0 = left, 1 = right
    const int b     = plane % BATCH;
    const float* __restrict__ base = (img == 0 ? left : right) + b * H * W;

    const int h0 = blockIdx.y * TH;          // output tile origin == input window origin
    const int w0 = blockIdx.x * TW;

    const int tid = threadIdx.y * TW + threadIdx.x;

    // Cooperative load of the (TH+8) x (TW+8) input tile (clamped; clamp only
    // feeds threads whose output pixel is out of range anyway).
    #pragma unroll
    for (int idx = tid; idx < IN_TH * IN_TW; idx += TW * TH) {
        int r = idx / IN_TW;
        int c = idx - r * IN_TW;
        int gr = h0 + r; if (gr > H - 1) gr = H - 1;
        int gc = w0 + c; if (gc > W - 1) gc = W - 1;
        tile[r][c] = base[gr * W + gc];
    }
    __syncthreads();

    const int ty = threadIdx.y;
    const int tx = threadIdx.x;
    const int oh = h0 + ty;
    const int ow = w0 + tx;
    if (oh >= HC || ow >= WC) return;

    const float center = tile[ty + RADIUS][tx + RADIUS];

    unsigned int b0 = 0u, b1 = 0u, b2 = 0u;
    int k = 0;
    #pragma unroll
    for (int i = 0; i < WIN; i++) {
        #pragma unroll
        for (int j = 0; j < WIN; j++) {
            if (i == RADIUS && j == RADIUS) continue;
            unsigned int bit = (tile[ty + i][tx + j] > center) ? 1u : 0u;
            if (k < 32)       b0 |= bit << k;
            else if (k < 64)  b1 |= bit << (k - 32);
            else              b2 |= bit << (k - 64);
            k++;
        }
    }

    g_census[(plane * HC + oh) * WC + ow] = make_uint4(b0, b1, b2, 0u);
}

__global__ __launch_bounds__(256)
void loss_kernel(const float* __restrict__ disp) {
    const int total = BATCH * HC * WC;
    const int idx = blockIdx.x * blockDim.x + threadIdx.x;

    unsigned int my_cost = 0u;
    unsigned int my_cnt  = 0u;

    if (idx < total) {
        const int w = idx % WC;
        const int t = idx / WC;
        const int h = t % HC;
        const int b = t / HC;

        const float d = disp[(b * H + (h + RADIUS)) * W + (w + RADIUS)];
        if (d > 0.0f) {
            int ti = (int)d;
            ti = ti < 0 ? 0 : (ti > MAX_DISP - 1 ? MAX_DISP - 1 : ti);
            const int widx = w + ti;

            const uint4 l = g_census[(b * HC + h) * WC + w];
            unsigned int c;
            if (widx < WC) {
                const uint4 r = g_census[((BATCH + b) * HC + h) * WC + widx];
                c = __popc(l.x ^ r.x) + __popc(l.y ^ r.y) + __popc(l.z ^ r.z);
            } else {
                c = __popc(l.x) + __popc(l.y) + __popc(l.z);
            }
            my_cost = c;
            my_cnt  = 1u;
        }
    }

    // Warp reduce
    #pragma unroll
    for (int off = 16; off > 0; off >>= 1) {
        my_cost += __shfl_down_sync(0xFFFFFFFFu, my_cost, off);
        my_cnt  += __shfl_down_sync(0xFFFFFFFFu, my_cnt,  off);
    }

    __shared__ unsigned int s_cost[8];
    __shared__ unsigned int s_cnt[8];
    const int lane = threadIdx.x & 31;
    const int warp = threadIdx.x >> 5;
    if (lane == 0) { s_cost[warp] = my_cost; s_cnt[warp] = my_cnt; }
    __syncthreads();

    if (warp == 0) {
        unsigned int c = (lane < 8) ? s_cost[lane] : 0u;
        unsigned int n = (lane < 8) ? s_cnt[lane]  : 0u;
        #pragma unroll
        for (int off = 4; off > 0; off >>= 1) {
            c += __shfl_down_sync(0xFFFFFFFFu, c, off);
            n += __shfl_down_sync(0xFFFFFFFFu, n, off);
        }
        if (lane == 0) {
            atomicAdd(&g_acc[0], c);
            atomicAdd(&g_acc[1], n);
        }
    }
}

__global__ void finalize_kernel(float* __restrict__ out) {
    out[0] = (float)g_acc[0] / ((float)g_acc[1] + 1e-6f);
}

extern "C" void kernel_launch(void* const* d_in, const int* in_sizes, int n_in,
                              void* d_out, int out_size) {
    const float* left  = (const float*)d_in[0];
    const float* right = (const float*)d_in[1];
    const float* disp  = (const float*)d_in[2];
    float* out = (float*)d_out;

    zero_kernel<<<1, 1>>>();

    dim3 cblk(TW, TH, 1);
    dim3 cgrd((WC + TW - 1) / TW, (HC + TH - 1) / TH, 2 * BATCH);
    census_kernel<<<cgrd, cblk>>>(left, right);

    const int total = BATCH * HC * WC;
    loss_kernel<<<(total + 255) / 256, 256>>>(disp);

    finalize_kernel<<<1, 1>>>(out);
}